// round 1
// baseline (speedup 1.0000x reference)
#include <cuda_runtime.h>
#include <cstdint>

// Problem constants (fixed by the reference):
//   x:   [4096*64, 256] f32   row (b*64 + n), feature f
//   W:   [64, 256, 256] f32   node n, f, o
//   out: [4096*64, 256] f32   = (1/16) * sum_f x[b*64+n, f] * W[n, f, o]
//
// 64 independent GEMMs: A_n [4096 x 256] (row stride 64*256) @ B_n [256 x 256].

#define NUM_NODES 64
#define F_DIM     256
#define O_DIM     256
#define BATCH     4096
#define ROW_STRIDE (NUM_NODES * F_DIM)   // 16384 floats between consecutive b

#define BM 128
#define BN 128
#define BK 16
#define TM 8
#define TN 8

// ---- f32x2 packed-math helpers (FFMA2 is PTX-only on sm_103a) ----
__device__ __forceinline__ unsigned long long pack2(float lo, float hi) {
    unsigned long long r;
    asm("mov.b64 %0, {%1, %2};" : "=l"(r) : "f"(lo), "f"(hi));
    return r;
}
__device__ __forceinline__ unsigned long long fma2(unsigned long long a,
                                                   unsigned long long b,
                                                   unsigned long long c) {
    unsigned long long d;
    asm("fma.rn.f32x2 %0, %1, %2, %3;" : "=l"(d) : "l"(a), "l"(b), "l"(c));
    return d;
}
__device__ __forceinline__ void unpack2(unsigned long long v, float& lo, float& hi) {
    asm("mov.b64 {%0, %1}, %2;" : "=f"(lo), "=f"(hi) : "l"(v));
}

__global__ __launch_bounds__(256, 2)
void node_gemm_f32x2_kernel(const float* __restrict__ x,
                            const float* __restrict__ W,
                            float* __restrict__ out)
{
    const int node = blockIdx.z;
    const int m0   = blockIdx.y * BM;   // batch-row tile
    const int n0   = blockIdx.x * BN;   // output-dim tile

    const float* A = x   + (size_t)node * F_DIM;                 // row stride ROW_STRIDE
    const float* B = W   + (size_t)node * F_DIM * O_DIM;         // row stride O_DIM
    float*       C = out + (size_t)node * O_DIM;                 // row stride ROW_STRIDE

    __shared__ float As[BK][BM];   // transposed: As[k][m], m contiguous -> LDS.64 row pairs
    __shared__ float Bs[BK][BN];

    const int tid = threadIdx.x;
    const int tx  = tid & 15;      // 0..15 -> n micro-tile
    const int ty  = tid >> 4;      // 0..15 -> m micro-tile

    // acc2[i][j] holds rows (ty*8+2i, ty*8+2i+1), col (tx*8+j) packed as f32x2
    unsigned long long acc2[TM / 2][TN];
    #pragma unroll
    for (int i = 0; i < TM / 2; i++)
        #pragma unroll
        for (int j = 0; j < TN; j++) acc2[i][j] = 0ull;

    for (int k0 = 0; k0 < F_DIM; k0 += BK) {
        // ---- cooperative tile load: 512 float4 each for A and B, 2 per thread ----
        #pragma unroll
        for (int r = 0; r < 2; r++) {
            const int l = tid + r * 256;

            // A: tile element (m = l/4, k4 = (l%4)*4); store transposed into As[k][m]
            const int am  = l >> 2;
            const int ak4 = (l & 3) << 2;
            float4 av = *reinterpret_cast<const float4*>(
                &A[(size_t)(m0 + am) * ROW_STRIDE + k0 + ak4]);
            As[ak4 + 0][am] = av.x;
            As[ak4 + 1][am] = av.y;
            As[ak4 + 2][am] = av.z;
            As[ak4 + 3][am] = av.w;

            // B: tile element (k = l/32, n4 = (l%32)*4); direct layout Bs[k][n]
            const int bk  = l >> 5;
            const int bn4 = (l & 31) << 2;
            *reinterpret_cast<float4*>(&Bs[bk][bn4]) =
                *reinterpret_cast<const float4*>(
                    &B[(size_t)(k0 + bk) * O_DIM + n0 + bn4]);
        }
        __syncthreads();

        #pragma unroll
        for (int k = 0; k < BK; k++) {
            // a pairs: rows (ty*8+2i, +1) are adjacent in As[k][*] -> direct 64-bit load
            const unsigned long long* As64 =
                reinterpret_cast<const unsigned long long*>(&As[k][0]);
            unsigned long long a2[TM / 2];
            #pragma unroll
            for (int i = 0; i < TM / 2; i++) a2[i] = As64[ty * 4 + i];

            // b broadcast pairs (b, b)
            unsigned long long b2[TN];
            #pragma unroll
            for (int j = 0; j < TN; j++) {
                float bv = Bs[k][tx * TN + j];
                b2[j] = pack2(bv, bv);
            }

            #pragma unroll
            for (int i = 0; i < TM / 2; i++)
                #pragma unroll
                for (int j = 0; j < TN; j++)
                    acc2[i][j] = fma2(a2[i], b2[j], acc2[i][j]);
        }
        __syncthreads();
    }

    // ---- epilogue: unpack, scale by 1/sqrt(256) = 1/16 exactly, vectorized store ----
    const float scale = 0.0625f;
    #pragma unroll
    for (int i = 0; i < TM / 2; i++) {
        float r0[TN], r1[TN];
        #pragma unroll
        for (int j = 0; j < TN; j++) unpack2(acc2[i][j], r0[j], r1[j]);

        const size_t row0 = (size_t)(m0 + ty * TM + 2 * i)     * ROW_STRIDE;
        const size_t row1 = (size_t)(m0 + ty * TM + 2 * i + 1) * ROW_STRIDE;
        #pragma unroll
        for (int j = 0; j < TN; j += 4) {
            float4 v0, v1;
            v0.x = r0[j]     * scale; v0.y = r0[j + 1] * scale;
            v0.z = r0[j + 2] * scale; v0.w = r0[j + 3] * scale;
            v1.x = r1[j]     * scale; v1.y = r1[j + 1] * scale;
            v1.z = r1[j + 2] * scale; v1.w = r1[j + 3] * scale;
            *reinterpret_cast<float4*>(&C[row0 + n0 + tx * TN + j]) = v0;
            *reinterpret_cast<float4*>(&C[row1 + n0 + tx * TN + j]) = v1;
        }
    }
}

extern "C" void kernel_launch(void* const* d_in, const int* in_sizes, int n_in,
                              void* d_out, int out_size)
{
    // metadata order: x (f32), batch (int64, unused), W (f32)
    const float* x = (const float*)d_in[0];
    const float* W = (const float*)d_in[2];
    float*     out = (float*)d_out;

    dim3 grid(O_DIM / BN, BATCH / BM, NUM_NODES);   // (2, 32, 64)
    node_gemm_f32x2_kernel<<<grid, 256>>>(x, W, out);
}

// round 2
// speedup vs baseline: 1.6219x; 1.6219x over previous
#include <cuda_runtime.h>
#include <cstdint>

// Problem constants (fixed by the reference):
//   x:   [4096*64, 256] f32   row (b*64 + n), feature f
//   W:   [64, 256, 256] f32   node n, f, o
//   out: [4096*64, 256] f32   = (1/16) * sum_f x[b*64+n, f] * W[n, f, o]
//
// 64 independent GEMMs: A_n [4096 x 256] (row stride 64*256) @ B_n [256 x 256].

#define NUM_NODES 64
#define F_DIM     256
#define O_DIM     256
#define BATCH     4096
#define ROW_STRIDE (NUM_NODES * F_DIM)   // 16384 floats between consecutive b

#define BM 128
#define BN 128
#define BK 16
#define TM 8
#define TN 8

// ---- f32x2 packed-math helpers (FFMA2 is PTX-only on sm_103a) ----
__device__ __forceinline__ unsigned long long pack2(float lo, float hi) {
    unsigned long long r;
    asm("mov.b64 %0, {%1, %2};" : "=l"(r) : "f"(lo), "f"(hi));
    return r;
}
__device__ __forceinline__ unsigned long long fma2(unsigned long long a,
                                                   unsigned long long b,
                                                   unsigned long long c) {
    unsigned long long d;
    asm("fma.rn.f32x2 %0, %1, %2, %3;" : "=l"(d) : "l"(a), "l"(b), "l"(c));
    return d;
}
__device__ __forceinline__ void unpack2(unsigned long long v, float& lo, float& hi) {
    asm("mov.b64 {%0, %1}, %2;" : "=f"(lo), "=f"(hi) : "l"(v));
}

__global__ __launch_bounds__(256, 2)
void node_gemm_f32x2_kernel(const float* __restrict__ x,
                            const float* __restrict__ W,
                            float* __restrict__ out)
{
    const int node = blockIdx.z;
    const int m0   = blockIdx.y * BM;   // batch-row tile
    const int n0   = blockIdx.x * BN;   // output-dim tile

    const float* A = x   + (size_t)node * F_DIM;                 // row stride ROW_STRIDE
    const float* B = W   + (size_t)node * F_DIM * O_DIM;         // row stride O_DIM
    float*       C = out + (size_t)node * O_DIM;                 // row stride ROW_STRIDE

    __shared__ float As[BK][BM];   // transposed: As[k][m], m contiguous -> LDS.64 row pairs
    __shared__ float Bs[BK][BN];

    const int tid = threadIdx.x;
    const int tx  = tid & 15;      // 0..15 -> n micro-tile
    const int ty  = tid >> 4;      // 0..15 -> m micro-tile

    // acc2[i][j] holds rows (ty*8+2i, ty*8+2i+1), col (tx*8+j) packed as f32x2
    unsigned long long acc2[TM / 2][TN];
    #pragma unroll
    for (int i = 0; i < TM / 2; i++)
        #pragma unroll
        for (int j = 0; j < TN; j++) acc2[i][j] = 0ull;

    for (int k0 = 0; k0 < F_DIM; k0 += BK) {
        // ---- cooperative tile load: 512 float4 each for A and B, 2 per thread ----
        #pragma unroll
        for (int r = 0; r < 2; r++) {
            const int l = tid + r * 256;

            // A: tile element (m = l/4, k4 = (l%4)*4); store transposed into As[k][m]
            const int am  = l >> 2;
            const int ak4 = (l & 3) << 2;
            float4 av = *reinterpret_cast<const float4*>(
                &A[(size_t)(m0 + am) * ROW_STRIDE + k0 + ak4]);
            As[ak4 + 0][am] = av.x;
            As[ak4 + 1][am] = av.y;
            As[ak4 + 2][am] = av.z;
            As[ak4 + 3][am] = av.w;

            // B: tile element (k = l/32, n4 = (l%32)*4); direct layout Bs[k][n]
            const int bk  = l >> 5;
            const int bn4 = (l & 31) << 2;
            *reinterpret_cast<float4*>(&Bs[bk][bn4]) =
                *reinterpret_cast<const float4*>(
                    &B[(size_t)(k0 + bk) * O_DIM + n0 + bn4]);
        }
        __syncthreads();

        #pragma unroll
        for (int k = 0; k < BK; k++) {
            // a pairs: rows (ty*8+2i, +1) are adjacent in As[k][*] -> direct 64-bit load
            const unsigned long long* As64 =
                reinterpret_cast<const unsigned long long*>(&As[k][0]);
            unsigned long long a2[TM / 2];
            #pragma unroll
            for (int i = 0; i < TM / 2; i++) a2[i] = As64[ty * 4 + i];

            // b broadcast pairs (b, b)
            unsigned long long b2[TN];
            #pragma unroll
            for (int j = 0; j < TN; j++) {
                float bv = Bs[k][tx * TN + j];
                b2[j] = pack2(bv, bv);
            }

            #pragma unroll
            for (int i = 0; i < TM / 2; i++)
                #pragma unroll
                for (int j = 0; j < TN; j++)
                    acc2[i][j] = fma2(a2[i], b2[j], acc2[i][j]);
        }
        __syncthreads();
    }

    // ---- epilogue: unpack, scale by 1/sqrt(256) = 1/16 exactly, vectorized store ----
    const float scale = 0.0625f;
    #pragma unroll
    for (int i = 0; i < TM / 2; i++) {
        float r0[TN], r1[TN];
        #pragma unroll
        for (int j = 0; j < TN; j++) unpack2(acc2[i][j], r0[j], r1[j]);

        const size_t row0 = (size_t)(m0 + ty * TM + 2 * i)     * ROW_STRIDE;
        const size_t row1 = (size_t)(m0 + ty * TM + 2 * i + 1) * ROW_STRIDE;
        #pragma unroll
        for (int j = 0; j < TN; j += 4) {
            float4 v0, v1;
            v0.x = r0[j]     * scale; v0.y = r0[j + 1] * scale;
            v0.z = r0[j + 2] * scale; v0.w = r0[j + 3] * scale;
            v1.x = r1[j]     * scale; v1.y = r1[j + 1] * scale;
            v1.z = r1[j + 2] * scale; v1.w = r1[j + 3] * scale;
            *reinterpret_cast<float4*>(&C[row0 + n0 + tx * TN + j]) = v0;
            *reinterpret_cast<float4*>(&C[row1 + n0 + tx * TN + j]) = v1;
        }
    }
}

extern "C" void kernel_launch(void* const* d_in, const int* in_sizes, int n_in,
                              void* d_out, int out_size)
{
    // metadata order: x (f32), batch (int64, unused), W (f32)
    const float* x = (const float*)d_in[0];
    const float* W = (const float*)d_in[2];
    float*     out = (float*)d_out;

    dim3 grid(O_DIM / BN, BATCH / BM, NUM_NODES);   // (2, 32, 64)
    node_gemm_f32x2_kernel<<<grid, 256>>>(x, W, out);
}

// round 5
// speedup vs baseline: 3.7092x; 2.2870x over previous
#include <cuda_runtime.h>
#include <cuda_bf16.h>
#include <cstdint>

// out[b*64+n][o] = (1/16) * sum_f x[b*64+n][f] * W[n][f][o]
// 64 GEMMs: A_n [4096 x 256] (row stride 16384 floats) @ B_n [256 x 256].
// Path: mma.sync bf16 (HMMA) with 3-term bf16 split (hi*hi + lo*hi + hi*lo).

#define NUM_NODES 64
#define BATCH     4096
#define RS        16384      // x/out row stride in floats

#define BM 128
#define NCHUNK 8
#define THREADS 512

// SMEM byte offsets: A tiles 8KB (128 rows x 64B), B tiles 16KB (256 rows x 64B)
#define AHI(s) ((s) * 8192)
#define ALO(s) (16384 + (s) * 8192)
#define BHI(s) (32768 + (s) * 16384)
#define BLO(s) (65536 + (s) * 16384)
#define SMEM_TOTAL 98304

// W pre-split + pre-swizzled: g_W*[ (node*8 + chunk)*16384 + swz(n*64 + kl*2) ]
__device__ __align__(16) unsigned char g_Whi[NUM_NODES * 8 * 16384];
__device__ __align__(16) unsigned char g_Wlo[NUM_NODES * 8 * 16384];

// ======================= helpers =======================
__device__ __forceinline__ uint32_t swz(uint32_t x) { return x ^ ((x >> 3) & 0x70); }
__device__ __forceinline__ uint32_t smem_u32(const void* p) {
    uint32_t a;
    asm("{ .reg .u64 t; cvta.to.shared.u64 t, %1; cvt.u32.u64 %0, t; }" : "=r"(a) : "l"(p));
    return a;
}
__device__ __forceinline__ void cp16(uint32_t d, const void* s) {
    asm volatile("cp.async.cg.shared.global [%0], [%1], 16;" :: "r"(d), "l"(s) : "memory");
}
__device__ __forceinline__ void ldmx4(uint32_t* r, uint32_t a) {
    asm volatile("ldmatrix.sync.aligned.m8n8.x4.shared.b16 {%0,%1,%2,%3}, [%4];"
                 : "=r"(r[0]), "=r"(r[1]), "=r"(r[2]), "=r"(r[3]) : "r"(a));
}
__device__ __forceinline__ void mma16816(float* c, const uint32_t* a, uint32_t b0, uint32_t b1) {
    asm volatile(
        "mma.sync.aligned.m16n8k16.row.col.f32.bf16.bf16.f32 "
        "{%0,%1,%2,%3}, {%4,%5,%6,%7}, {%8,%9}, {%0,%1,%2,%3};"
        : "+f"(c[0]), "+f"(c[1]), "+f"(c[2]), "+f"(c[3])
        : "r"(a[0]), "r"(a[1]), "r"(a[2]), "r"(a[3]), "r"(b0), "r"(b1));
}
__device__ __forceinline__ uint32_t packbf2(__nv_bfloat16 a, __nv_bfloat16 b) {
    return (uint32_t)__bfloat16_as_ushort(a) | ((uint32_t)__bfloat16_as_ushort(b) << 16);
}
__device__ __forceinline__ void split1(float v, __nv_bfloat16& h, __nv_bfloat16& l) {
    h = __float2bfloat16(v);
    l = __float2bfloat16(v - __bfloat162float(h));
}
__device__ __forceinline__ void sts8(uint32_t addr, uint32_t a, uint32_t b) {
    asm volatile("st.shared.v2.b32 [%0], {%1,%2};" :: "r"(addr), "r"(a), "r"(b) : "memory");
}

// ======================= prep: W -> split bf16, swizzled tiles =======================
__global__ __launch_bounds__(256)
void prep_w(const float* __restrict__ W) {
    __shared__ __align__(16) unsigned char shi[16384];
    __shared__ __align__(16) unsigned char slo[16384];
    const int node = blockIdx.x >> 3;
    const int c    = blockIdx.x & 7;
    const int o    = threadIdx.x;        // n index, coalesced LDG across lanes

    const float* src = W + (size_t)node * 65536 + (size_t)c * 32 * 256 + o;
    #pragma unroll 4
    for (int fl = 0; fl < 32; fl++) {
        float v = src[(size_t)fl * 256];
        __nv_bfloat16 h, l;
        split1(v, h, l);
        const uint32_t ad = swz((uint32_t)(o * 64 + fl * 2));
        *reinterpret_cast<__nv_bfloat16*>(shi + ad) = h;
        *reinterpret_cast<__nv_bfloat16*>(slo + ad) = l;
    }
    __syncthreads();

    const size_t off = (size_t)blockIdx.x * 16384;
    const float4* ph = reinterpret_cast<const float4*>(shi);
    const float4* pl = reinterpret_cast<const float4*>(slo);
    float4* dh = reinterpret_cast<float4*>(g_Whi + off);
    float4* dl = reinterpret_cast<float4*>(g_Wlo + off);
    #pragma unroll
    for (int i = 0; i < 4; i++) {
        const int idx = threadIdx.x + i * 256;
        dh[idx] = ph[idx];
        dl[idx] = pl[idx];
    }
}

// ======================= main GEMM =======================
__global__ __launch_bounds__(THREADS, 1)
void node_gemm_hmma(const float* __restrict__ x, float* __restrict__ out) {
    extern __shared__ unsigned char sm[];
    const uint32_t smb = smem_u32(sm);
    const int t    = threadIdx.x;
    const int lane = t & 31;
    const int wid  = t >> 5;
    const int wm   = wid >> 2;      // 0..3 -> m offset wm*32
    const int wn   = wid & 3;       // 0..3 -> n offset wn*64
    const int node = blockIdx.y;
    const int m0   = blockIdx.x * BM;

    // ---- A global-load role: row = wid*8 + (lane&7), quarter aq4 = (lane>>3)&3 ----
    const int arow = wid * 8 + (lane & 7);
    const int aq4  = (lane >> 3) & 3;
    const float* ag = x + (size_t)node * 256 + (size_t)(m0 + arow) * RS;
    const uint32_t asts0 = swz((uint32_t)(arow * 64 + aq4 * 8));
    const uint32_t asts1 = swz((uint32_t)(arow * 64 + 32 + aq4 * 8));

    // ---- fragment ldmatrix LINEAR base offsets; swz applied per use.
    //      (+1024 / +g*1024 row jumps are swizzle-invariant: they change only
    //       row bits >= 4, which do not feed the swizzle mask.) ----
    const int aq = lane >> 3;
    const uint32_t aoff_lin = (uint32_t)((wm * 32 + (aq & 1) * 8 + (lane & 7)) * 64 +
                                         (aq >> 1) * 16);
    const uint32_t boff_lin = (uint32_t)((wn * 64 + ((lane >> 4) & 1) * 8 + (lane & 7)) * 64 +
                                         ((lane >> 3) & 1) * 16);

    float acc[2][8][4];
    #pragma unroll
    for (int mi = 0; mi < 2; mi++)
        #pragma unroll
        for (int nf = 0; nf < 8; nf++)
            #pragma unroll
            for (int r = 0; r < 4; r++) acc[mi][nf][r] = 0.f;

    auto cpB = [&](int c, int s) {
        const size_t gb = (size_t)(node * 8 + c) * 16384;
        const uint32_t o1 = (uint32_t)t * 16, o2 = (uint32_t)(t + 512) * 16;
        cp16(smb + BHI(s) + o1, g_Whi + gb + o1);
        cp16(smb + BHI(s) + o2, g_Whi + gb + o2);
        cp16(smb + BLO(s) + o1, g_Wlo + gb + o1);
        cp16(smb + BLO(s) + o2, g_Wlo + gb + o2);
        asm volatile("cp.async.commit_group;" ::: "memory");
    };
    auto stsA = [&](int s, const float4& v0, const float4& v1) {
        uint32_t h01, h23, l01, l23;
        __nv_bfloat16 hx, lx, hy, ly;
        split1(v0.x, hx, lx); split1(v0.y, hy, ly); h01 = packbf2(hx, hy); l01 = packbf2(lx, ly);
        split1(v0.z, hx, lx); split1(v0.w, hy, ly); h23 = packbf2(hx, hy); l23 = packbf2(lx, ly);
        sts8(smb + AHI(s) + asts0, h01, h23);
        sts8(smb + ALO(s) + asts0, l01, l23);
        split1(v1.x, hx, lx); split1(v1.y, hy, ly); h01 = packbf2(hx, hy); l01 = packbf2(lx, ly);
        split1(v1.z, hx, lx); split1(v1.w, hy, ly); h23 = packbf2(hx, hy); l23 = packbf2(lx, ly);
        sts8(smb + AHI(s) + asts1, h01, h23);
        sts8(smb + ALO(s) + asts1, l01, l23);
    };

    // ---- prologue: chunk 0 ----
    cpB(0, 0);
    {
        float4 v0 = *reinterpret_cast<const float4*>(ag + 0 + aq4 * 4);
        float4 v1 = *reinterpret_cast<const float4*>(ag + 16 + aq4 * 4);
        stsA(0, v0, v1);
    }

    // ---- mainloop ----
    for (int c = 0; c < NCHUNK; c++) {
        const int s = c & 1;
        float4 nv0, nv1;
        if (c < NCHUNK - 1) {
            nv0 = *reinterpret_cast<const float4*>(ag + (c + 1) * 32 + aq4 * 4);
            nv1 = *reinterpret_cast<const float4*>(ag + (c + 1) * 32 + 16 + aq4 * 4);
            cpB(c + 1, 1 - s);
            asm volatile("cp.async.wait_group 1;" ::: "memory");
        } else {
            asm volatile("cp.async.wait_group 0;" ::: "memory");
        }
        __syncthreads();   // stage s ready: B arrived, everyone's A STS done

        const uint32_t ah = smb + AHI(s), al = smb + ALO(s);
        const uint32_t bh = smb + BHI(s), bl = smb + BLO(s);

        #pragma unroll
        for (int h = 0; h < 2; h++) {
            const uint32_t aswz = swz(aoff_lin + h * 32);   // correct per-k-half swizzle
            const uint32_t bswz = swz(boff_lin + h * 32);
            uint32_t Ah[2][4], Al[2][4], B[4][4];
            ldmx4(Ah[0], ah + aswz);
            ldmx4(Ah[1], ah + aswz + 1024);
            ldmx4(Al[0], al + aswz);
            ldmx4(Al[1], al + aswz + 1024);
            #pragma unroll
            for (int g = 0; g < 4; g++) ldmx4(B[g], bh + bswz + g * 1024);

            #pragma unroll
            for (int g = 0; g < 4; g++)
                #pragma unroll
                for (int gg = 0; gg < 2; gg++) {
                    const int nf = 2 * g + gg;
                    mma16816(acc[0][nf], Ah[0], B[g][gg * 2], B[g][gg * 2 + 1]);
                    mma16816(acc[1][nf], Ah[1], B[g][gg * 2], B[g][gg * 2 + 1]);
                    mma16816(acc[0][nf], Al[0], B[g][gg * 2], B[g][gg * 2 + 1]);
                    mma16816(acc[1][nf], Al[1], B[g][gg * 2], B[g][gg * 2 + 1]);
                }

            #pragma unroll
            for (int g = 0; g < 4; g++) ldmx4(B[g], bl + bswz + g * 1024);
            #pragma unroll
            for (int g = 0; g < 4; g++)
                #pragma unroll
                for (int gg = 0; gg < 2; gg++) {
                    const int nf = 2 * g + gg;
                    mma16816(acc[0][nf], Ah[0], B[g][gg * 2], B[g][gg * 2 + 1]);
                    mma16816(acc[1][nf], Ah[1], B[g][gg * 2], B[g][gg * 2 + 1]);
                }
        }

        if (c < NCHUNK - 1) stsA(1 - s, nv0, nv1);
        __syncthreads();   // protect stage s from next iteration's cp.async
    }

    // ---- epilogue: registers -> gmem, scale 1/16 ----
    const float sc = 0.0625f;
    float* ob = out + (size_t)node * 256;
    const int erow  = m0 + wm * 32 + (lane >> 2);
    const int ecol0 = wn * 64 + (lane & 3) * 2;
    #pragma unroll
    for (int mi = 0; mi < 2; mi++) {
        #pragma unroll
        for (int nf = 0; nf < 8; nf++) {
            float* p0 = ob + (size_t)(erow + mi * 16) * RS + ecol0 + nf * 8;
            float* p1 = p0 + (size_t)8 * RS;
            float2 v0, v1;
            v0.x = acc[mi][nf][0] * sc; v0.y = acc[mi][nf][1] * sc;
            v1.x = acc[mi][nf][2] * sc; v1.y = acc[mi][nf][3] * sc;
            *reinterpret_cast<float2*>(p0) = v0;
            *reinterpret_cast<float2*>(p1) = v1;
        }
    }
}

// ======================= launch =======================
extern "C" void kernel_launch(void* const* d_in, const int* in_sizes, int n_in,
                              void* d_out, int out_size)
{
    const float* x = (const float*)d_in[0];   // [262144, 256] f32
    const float* W = (const float*)d_in[2];   // [64, 256, 256] f32
    float*     out = (float*)d_out;

    cudaFuncSetAttribute(node_gemm_hmma, cudaFuncAttributeMaxDynamicSharedMemorySize, SMEM_TOTAL);

    prep_w<<<NUM_NODES * 8, 256>>>(W);
    node_gemm_hmma<<<dim3(BATCH / BM, NUM_NODES), THREADS, SMEM_TOTAL>>>(x, out);
}

// round 6
// speedup vs baseline: 3.9545x; 1.0661x over previous
#include <cuda_runtime.h>
#include <cuda_bf16.h>
#include <cstdint>

// out[b*64+n][o] = (1/16) * sum_f x[b*64+n][f] * W[n][f][o]
// 64 GEMMs: A_n [4096 x 256] (row stride 16384 floats) @ B_n [256 x 256].
// bf16 3-term split HMMA. 256 threads, 8 warps @ 64x64 warp tile, 3-stage pipe.

#define NUM_NODES 64
#define BATCH     4096
#define RS        16384

#define BM 128
#define NCHUNK 8
#define THREADS 256

// stage layout (bytes): Ahi 8K | Alo 8K | Bhi 16K | Blo 16K = 48K per stage
#define STG  49152
#define OAH  0
#define OAL  8192
#define OBH  16384
#define OBL  32768
#define SMEM_TOTAL (3 * STG)   // 147456

// W pre-split + pre-swizzled: g_W*[ (node*8 + chunk)*16384 + swz(n*64 + kl*2) ]
__device__ __align__(16) unsigned char g_Whi[NUM_NODES * 8 * 16384];
__device__ __align__(16) unsigned char g_Wlo[NUM_NODES * 8 * 16384];

// ======================= helpers =======================
__device__ __forceinline__ uint32_t swz(uint32_t x) { return x ^ ((x >> 3) & 0x70); }
__device__ __forceinline__ uint32_t smem_u32(const void* p) {
    uint32_t a;
    asm("{ .reg .u64 t; cvta.to.shared.u64 t, %1; cvt.u32.u64 %0, t; }" : "=r"(a) : "l"(p));
    return a;
}
__device__ __forceinline__ void cp16(uint32_t d, const void* s) {
    asm volatile("cp.async.cg.shared.global [%0], [%1], 16;" :: "r"(d), "l"(s) : "memory");
}
__device__ __forceinline__ void ldmx4(uint32_t* r, uint32_t a) {
    asm volatile("ldmatrix.sync.aligned.m8n8.x4.shared.b16 {%0,%1,%2,%3}, [%4];"
                 : "=r"(r[0]), "=r"(r[1]), "=r"(r[2]), "=r"(r[3]) : "r"(a));
}
__device__ __forceinline__ void mma16816(float* c, const uint32_t* a, uint32_t b0, uint32_t b1) {
    asm volatile(
        "mma.sync.aligned.m16n8k16.row.col.f32.bf16.bf16.f32 "
        "{%0,%1,%2,%3}, {%4,%5,%6,%7}, {%8,%9}, {%0,%1,%2,%3};"
        : "+f"(c[0]), "+f"(c[1]), "+f"(c[2]), "+f"(c[3])
        : "r"(a[0]), "r"(a[1]), "r"(a[2]), "r"(a[3]), "r"(b0), "r"(b1));
}
__device__ __forceinline__ uint32_t packbf2(__nv_bfloat16 a, __nv_bfloat16 b) {
    return (uint32_t)__bfloat16_as_ushort(a) | ((uint32_t)__bfloat16_as_ushort(b) << 16);
}
__device__ __forceinline__ void split1(float v, __nv_bfloat16& h, __nv_bfloat16& l) {
    h = __float2bfloat16(v);
    l = __float2bfloat16(v - __bfloat162float(h));
}
__device__ __forceinline__ void sts8(uint32_t addr, uint32_t a, uint32_t b) {
    asm volatile("st.shared.v2.b32 [%0], {%1,%2};" :: "r"(addr), "r"(a), "r"(b) : "memory");
}

// ======================= prep: W -> split bf16, swizzled tiles =======================
__global__ __launch_bounds__(256)
void prep_w(const float* __restrict__ W) {
    __shared__ __align__(16) unsigned char shi[16384];
    __shared__ __align__(16) unsigned char slo[16384];
    const int node = blockIdx.x >> 3;
    const int c    = blockIdx.x & 7;
    const int o    = threadIdx.x;

    const float* src = W + (size_t)node * 65536 + (size_t)c * 32 * 256 + o;
    #pragma unroll 4
    for (int fl = 0; fl < 32; fl++) {
        float v = src[(size_t)fl * 256];
        __nv_bfloat16 h, l;
        split1(v, h, l);
        const uint32_t ad = swz((uint32_t)(o * 64 + fl * 2));
        *reinterpret_cast<__nv_bfloat16*>(shi + ad) = h;
        *reinterpret_cast<__nv_bfloat16*>(slo + ad) = l;
    }
    __syncthreads();

    const size_t off = (size_t)blockIdx.x * 16384;
    const float4* ph = reinterpret_cast<const float4*>(shi);
    const float4* pl = reinterpret_cast<const float4*>(slo);
    float4* dh = reinterpret_cast<float4*>(g_Whi + off);
    float4* dl = reinterpret_cast<float4*>(g_Wlo + off);
    #pragma unroll
    for (int i = 0; i < 4; i++) {
        const int idx = threadIdx.x + i * 256;
        dh[idx] = ph[idx];
        dl[idx] = pl[idx];
    }
}

// ======================= main GEMM =======================
__global__ __launch_bounds__(THREADS, 1)
void node_gemm_hmma(const float* __restrict__ x, float* __restrict__ out) {
    extern __shared__ unsigned char sm[];
    const uint32_t smb = smem_u32(sm);
    const int t    = threadIdx.x;
    const int lane = t & 31;
    const int wid  = t >> 5;
    const int wm   = wid >> 2;      // 0..1 -> m offset wm*64
    const int wn   = wid & 3;       // 0..3 -> n offset wn*64
    const int node = blockIdx.y;
    const int m0   = blockIdx.x * BM;

    // ---- A global-load role: each thread owns 16 floats of one row per chunk ----
    const int arow = t >> 1;            // 0..127
    const int ah16 = (t & 1) * 16;      // column half (16 floats)
    const float* ag = x + (size_t)node * 256 + (size_t)(m0 + arow) * RS + ah16;
    uint32_t asts[4];
    #pragma unroll
    for (int i = 0; i < 4; i++)
        asts[i] = swz((uint32_t)(arow * 64 + ah16 * 2 + i * 8));

    // ---- fragment ldmatrix LINEAR base offsets; swz applied per (half) use.
    //      row jumps of 1024*k post-swizzle are swizzle-invariant. ----
    const int aq = lane >> 3;
    const uint32_t aoff_lin = (uint32_t)((wm * 64 + (aq & 1) * 8 + (lane & 7)) * 64 +
                                         (aq >> 1) * 16);
    const uint32_t boff_lin = (uint32_t)((wn * 64 + ((lane >> 4) & 1) * 8 + (lane & 7)) * 64 +
                                         ((lane >> 3) & 1) * 16);

    float acc[4][8][4];
    #pragma unroll
    for (int mi = 0; mi < 4; mi++)
        #pragma unroll
        for (int nf = 0; nf < 8; nf++)
            #pragma unroll
            for (int r = 0; r < 4; r++) acc[mi][nf][r] = 0.f;

    auto cpB = [&](int c, int s) {
        const size_t gb = (size_t)(node * 8 + c) * 16384;
        const uint32_t sb = smb + s * STG;
        #pragma unroll
        for (int j = 0; j < 4; j++) {
            const uint32_t o = (uint32_t)(t + j * 256) * 16;
            cp16(sb + OBH + o, g_Whi + gb + o);
            cp16(sb + OBL + o, g_Wlo + gb + o);
        }
        asm volatile("cp.async.commit_group;" ::: "memory");
    };
    auto stsA = [&](int s, const float4* v) {
        const uint32_t sb = smb + s * STG;
        #pragma unroll
        for (int i = 0; i < 4; i++) {
            __nv_bfloat16 hx, lx, hy, ly, hz, lz, hw, lw;
            split1(v[i].x, hx, lx); split1(v[i].y, hy, ly);
            split1(v[i].z, hz, lz); split1(v[i].w, hw, lw);
            sts8(sb + OAH + asts[i], packbf2(hx, hy), packbf2(hz, hw));
            sts8(sb + OAL + asts[i], packbf2(lx, ly), packbf2(lz, lw));
        }
    };
    auto ldA = [&](int c, float4* v) {
        #pragma unroll
        for (int i = 0; i < 4; i++)
            v[i] = *reinterpret_cast<const float4*>(ag + c * 32 + i * 4);
    };

    // ---- prologue: chunks 0,1 ----
    cpB(0, 0);
    {
        float4 a0[4];
        ldA(0, a0);
        stsA(0, a0);
    }
    cpB(1, 1);
    {
        float4 a1[4];
        ldA(1, a1);
        stsA(1, a1);
    }
    asm volatile("cp.async.wait_group 1;" ::: "memory");
    __syncthreads();

    // ---- mainloop: one barrier per chunk ----
    #pragma unroll
    for (int c = 0; c < NCHUNK; c++) {
        const int s = c % 3;
        const uint32_t sb = smb + s * STG;

        float4 av[4];
        if (c + 2 < NCHUNK) {
            ldA(c + 2, av);               // LDG latency hidden by compute below
            cpB(c + 2, (c + 2) % 3);
        }

        #pragma unroll
        for (int h = 0; h < 2; h++) {
            const uint32_t aswz = swz(aoff_lin + h * 32);
            const uint32_t bswz = swz(boff_lin + h * 32);
            uint32_t Ah[4][4], Al[4][4], B[4][4];
            #pragma unroll
            for (int mi = 0; mi < 4; mi++) ldmx4(Ah[mi], sb + OAH + aswz + mi * 1024);
            #pragma unroll
            for (int mi = 0; mi < 4; mi++) ldmx4(Al[mi], sb + OAL + aswz + mi * 1024);
            #pragma unroll
            for (int g = 0; g < 4; g++) ldmx4(B[g], sb + OBH + bswz + g * 1024);

            #pragma unroll
            for (int g = 0; g < 4; g++)
                #pragma unroll
                for (int gg = 0; gg < 2; gg++) {
                    const int nf = 2 * g + gg;
                    #pragma unroll
                    for (int mi = 0; mi < 4; mi++)
                        mma16816(acc[mi][nf], Ah[mi], B[g][gg * 2], B[g][gg * 2 + 1]);
                    #pragma unroll
                    for (int mi = 0; mi < 4; mi++)
                        mma16816(acc[mi][nf], Al[mi], B[g][gg * 2], B[g][gg * 2 + 1]);
                }

            #pragma unroll
            for (int g = 0; g < 4; g++) ldmx4(B[g], sb + OBL + bswz + g * 1024);
            #pragma unroll
            for (int g = 0; g < 4; g++)
                #pragma unroll
                for (int gg = 0; gg < 2; gg++) {
                    const int nf = 2 * g + gg;
                    #pragma unroll
                    for (int mi = 0; mi < 4; mi++)
                        mma16816(acc[mi][nf], Ah[mi], B[g][gg * 2], B[g][gg * 2 + 1]);
                }
        }

        if (c + 2 < NCHUNK) stsA((c + 2) % 3, av);
        if (c < NCHUNK - 1) {
            if (c < NCHUNK - 2) {
                asm volatile("cp.async.wait_group 1;" ::: "memory");
            } else {
                asm volatile("cp.async.wait_group 0;" ::: "memory");
            }
            __syncthreads();
        }
    }

    // ---- epilogue: registers -> gmem, scale 1/16 ----
    const float sc = 0.0625f;
    float* ob = out + (size_t)node * 256;
    const int ecol0 = wn * 64 + (lane & 3) * 2;
    #pragma unroll
    for (int mi = 0; mi < 4; mi++) {
        const int erow = m0 + wm * 64 + mi * 16 + (lane >> 2);
        #pragma unroll
        for (int nf = 0; nf < 8; nf++) {
            float* p0 = ob + (size_t)erow * RS + ecol0 + nf * 8;
            float* p1 = p0 + (size_t)8 * RS;
            float2 v0, v1;
            v0.x = acc[mi][nf][0] * sc; v0.y = acc[mi][nf][1] * sc;
            v1.x = acc[mi][nf][2] * sc; v1.y = acc[mi][nf][3] * sc;
            *reinterpret_cast<float2*>(p0) = v0;
            *reinterpret_cast<float2*>(p1) = v1;
        }
    }
}

// ======================= launch =======================
extern "C" void kernel_launch(void* const* d_in, const int* in_sizes, int n_in,
                              void* d_out, int out_size)
{
    const float* x = (const float*)d_in[0];   // [262144, 256] f32
    const float* W = (const float*)d_in[2];   // [64, 256, 256] f32
    float*     out = (float*)d_out;

    cudaFuncSetAttribute(node_gemm_hmma, cudaFuncAttributeMaxDynamicSharedMemorySize, SMEM_TOTAL);

    prep_w<<<NUM_NODES * 8, 256>>>(W);
    node_gemm_hmma<<<dim3(BATCH / BM, NUM_NODES), THREADS, SMEM_TOTAL>>>(x, out);
}